// round 12
// baseline (speedup 1.0000x reference)
#include <cuda_runtime.h>

// ---------------- problem-size constants ----------------
#define NMAX 50000
#define EMAX 800000
#define F1   64
#define F2   32
#define DIN  128
#define DOUT 128
#define PAD  128          // ELL row capacity (Poisson(16) max deg ~45; huge margin)

// ---------------- device scratch ----------------
__device__ int   g_cnt[NMAX];             // zero-init at load; re-zeroed by gemm3 tail
__device__ float g_dinv[NMAX];
__device__ int   g_ell[(long long)NMAX * PAD];
__device__ float g_h1[NMAX * F1];
__device__ float g_a1[NMAX * F1];
__device__ float g_h2[NMAX * F2];
__device__ float g_a2[NMAX * F2];
__device__ int   g_is64;

// ---------------- f32x2 helpers ----------------
__device__ __forceinline__ void fma2(unsigned long long& d,
                                     unsigned long long a,
                                     unsigned long long b) {
    asm("fma.rn.f32x2 %0, %1, %2, %0;" : "+l"(d) : "l"(a), "l"(b));
}
__device__ __forceinline__ unsigned long long dup2(float w) {
    unsigned long long r;
    asm("mov.b64 %0, {%1, %1};" : "=l"(r) : "f"(w));
    return r;
}
__device__ __forceinline__ float lo32(unsigned long long v) {
    return __uint_as_float((unsigned)(v & 0xffffffffull));
}
__device__ __forceinline__ float hi32(unsigned long long v) {
    return __uint_as_float((unsigned)(v >> 32));
}

// ---------------- edge-index dtype detection (1 block) ----------------
__global__ void detect_kernel(const int* __restrict__ w, int E) {
    __shared__ int any_nonzero;
    if (threadIdx.x == 0) any_nonzero = 0;
    __syncthreads();
    int stride = (2 * E) / 512;
    int idx = 2 * (threadIdx.x * stride) + 1;
    if (w[idx] != 0) atomicOr(&any_nonzero, 1);
    __syncthreads();
    if (threadIdx.x == 0) g_is64 = any_nonzero ? 0 : 1;
}

// ---------------- ELL build: count + scatter in ONE pass ----------------
__global__ void scatter_count_kernel(const int* __restrict__ w, int E) {
    int e = blockIdx.x * blockDim.x + threadIdx.x;
    if (e >= E) return;
    int s, d;
    if (g_is64) { s = w[2 * e]; d = w[2 * (E + e)]; }
    else        { s = w[e];     d = w[E + e];       }
    int p = atomicAdd(&g_cnt[d], 1);
    if (p < PAD) g_ell[(long long)d * PAD + p] = s;
}

__global__ void dinv_kernel(int n) {
    int i = blockIdx.x * blockDim.x + threadIdx.x;
    if (i < n) g_dinv[i] = rsqrtf((float)(g_cnt[i] + 1));   // +1 self loop
}

// ---------------- f32x2 GEMM: 4 nodes x 8 cols per thread --------------------
// TM=64 nodes/block, (TN/8)*16 threads. acc = 16 u64 = 32 regs -> ~6 blocks/SM.
// a-pairs natural from transposed Xs; b duplicated via mov.b64 (alu pipe).
template<int KIN, int KOUT, int TN, bool INACT, bool OBIAS, bool ZCNT>
__global__ void __launch_bounds__((TN / 8) * 16)
gemm_rt3(const float* __restrict__ A, const float* __restrict__ W,
         const float* __restrict__ ib, const float* __restrict__ ob,
         float* __restrict__ H, int n)
{
    constexpr int TM = 64;
    constexpr int TK = (KIN < 32) ? KIN : 32;
    constexpr int NTX = TN / 8;           // col groups of 8
    constexpr int NTY = TM / 4;           // node groups of 4 (16)
    constexpr int NTH = NTX * NTY;
    constexpr int XPITCH = TM + 4;        // 68 floats; kk*272B keeps 16B alignment

    __shared__ float Xs[TK * XPITCH];     // transposed: Xs[k][node]
    __shared__ float Ws[TK * TN];         // Ws[k][col]

    const int tid = threadIdx.x;
    const int tx = tid % NTX;
    const int ty = tid / NTX;
    const int nb = blockIdx.x * TM;
    const int jn = blockIdx.y * TN;
    const int valid = min(TM, n - nb);

    if (ZCNT && blockIdx.y == 0 && tid < TM) {
        int idx = nb + tid;
        if (idx < n) g_cnt[idx] = 0;
    }

    unsigned long long acc[2][8];         // [node-pair][col]
#pragma unroll
    for (int i = 0; i < 2; i++)
#pragma unroll
        for (int j = 0; j < 8; j++) acc[i][j] = 0ull;

    for (int kt = 0; kt < KIN; kt += TK) {
        // X tile: load float4 rows, transpose into Xs[k][node] (+bias/relu)
#pragma unroll
        for (int idx = tid; idx < TM * TK / 4; idx += NTH) {
            int r  = idx / (TK / 4);
            int kq = idx % (TK / 4);
            float4 v = make_float4(0.f, 0.f, 0.f, 0.f);
            if (r < valid)
                v = *reinterpret_cast<const float4*>(
                        A + (long long)(nb + r) * KIN + kt + kq * 4);
            if (INACT) {
                const float4 bb = *reinterpret_cast<const float4*>(ib + kt + kq * 4);
                v.x = fmaxf(v.x + bb.x, 0.f);
                v.y = fmaxf(v.y + bb.y, 0.f);
                v.z = fmaxf(v.z + bb.z, 0.f);
                v.w = fmaxf(v.w + bb.w, 0.f);
            }
            Xs[(kq * 4 + 0) * XPITCH + r] = v.x;
            Xs[(kq * 4 + 1) * XPITCH + r] = v.y;
            Xs[(kq * 4 + 2) * XPITCH + r] = v.z;
            Xs[(kq * 4 + 3) * XPITCH + r] = v.w;
        }
        // W tile (plain)
#pragma unroll
        for (int idx = tid; idx < TK * TN / 4; idx += NTH) {
            int kk = idx / (TN / 4);
            int jq = idx % (TN / 4);
            *reinterpret_cast<float4*>(Ws + kk * TN + jq * 4) =
                *reinterpret_cast<const float4*>(
                    W + (long long)(kt + kk) * KOUT + jn + jq * 4);
        }
        __syncthreads();

#pragma unroll
        for (int kk = 0; kk < TK; kk++) {
            // a: 4 nodes = 2 natural f32x2 pairs (one LDS.128)
            const ulonglong2 pa = *reinterpret_cast<const ulonglong2*>(
                Xs + kk * XPITCH + ty * 4);
            // b: 8 cols -> duplicated pairs
            const float4 b0 = *reinterpret_cast<const float4*>(Ws + kk * TN + tx * 8);
            const float4 b1 = *reinterpret_cast<const float4*>(Ws + kk * TN + tx * 8 + 4);
            unsigned long long pb[8];
            pb[0] = dup2(b0.x); pb[1] = dup2(b0.y); pb[2] = dup2(b0.z); pb[3] = dup2(b0.w);
            pb[4] = dup2(b1.x); pb[5] = dup2(b1.y); pb[6] = dup2(b1.z); pb[7] = dup2(b1.w);

#pragma unroll
            for (int j = 0; j < 8; j++) fma2(acc[0][j], pa.x, pb[j]);
#pragma unroll
            for (int j = 0; j < 8; j++) fma2(acc[1][j], pa.y, pb[j]);
        }
        __syncthreads();
    }

    float4 bo0 = make_float4(0.f, 0.f, 0.f, 0.f);
    float4 bo1 = make_float4(0.f, 0.f, 0.f, 0.f);
    if (OBIAS) {
        bo0 = *reinterpret_cast<const float4*>(ob + jn + tx * 8);
        bo1 = *reinterpret_cast<const float4*>(ob + jn + tx * 8 + 4);
    }
#pragma unroll
    for (int p = 0; p < 2; p++) {
#pragma unroll
        for (int half = 0; half < 2; half++) {
            int node = nb + ty * 4 + p * 2 + half;
            if (node < n) {
                float4 v0, v1;
                if (half == 0) {
                    v0 = make_float4(lo32(acc[p][0]), lo32(acc[p][1]),
                                     lo32(acc[p][2]), lo32(acc[p][3]));
                    v1 = make_float4(lo32(acc[p][4]), lo32(acc[p][5]),
                                     lo32(acc[p][6]), lo32(acc[p][7]));
                } else {
                    v0 = make_float4(hi32(acc[p][0]), hi32(acc[p][1]),
                                     hi32(acc[p][2]), hi32(acc[p][3]));
                    v1 = make_float4(hi32(acc[p][4]), hi32(acc[p][5]),
                                     hi32(acc[p][6]), hi32(acc[p][7]));
                }
                v0.x += bo0.x; v0.y += bo0.y; v0.z += bo0.z; v0.w += bo0.w;
                v1.x += bo1.x; v1.y += bo1.y; v1.z += bo1.z; v1.w += bo1.w;
                float* dst = H + (long long)node * KOUT + jn + tx * 8;
                *reinterpret_cast<float4*>(dst)     = v0;
                *reinterpret_cast<float4*>(dst + 4) = v1;
            }
        }
    }
}

// ---------------- ELL gather propagation: multi-stream warps ----------------
// out[v] = dinv[v] * ( dinv[v]*h[v] + sum_j dinv[src_j]*h[src_j] )
__global__ void __launch_bounds__(256)
prop64_kernel(const float* __restrict__ h, float* __restrict__ g, int n)
{
    const int v = (blockIdx.x * blockDim.x + threadIdx.x) >> 5;
    if (v >= n) return;
    const int lane = threadIdx.x & 31;
    const int half = lane >> 4;
    const int fl   = lane & 15;
    const int r1 = min(g_cnt[v], PAD);
    const float div = g_dinv[v];
    const int* __restrict__ row = g_ell + (long long)v * PAD;

    float4 acc = make_float4(0.f, 0.f, 0.f, 0.f);
    if (half == 0) {
        acc = *reinterpret_cast<const float4*>(h + (long long)v * F1 + fl * 4);
        acc.x *= div; acc.y *= div; acc.z *= div; acc.w *= div;
    }

    int j = half;
    for (; j + 6 < r1; j += 8) {
        int s0 = row[j], s1 = row[j + 2], s2 = row[j + 4], s3 = row[j + 6];
        float w0 = g_dinv[s0], w1 = g_dinv[s1], w2 = g_dinv[s2], w3 = g_dinv[s3];
        float4 v0 = *reinterpret_cast<const float4*>(h + (long long)s0 * F1 + fl * 4);
        float4 v1 = *reinterpret_cast<const float4*>(h + (long long)s1 * F1 + fl * 4);
        float4 v2 = *reinterpret_cast<const float4*>(h + (long long)s2 * F1 + fl * 4);
        float4 v3 = *reinterpret_cast<const float4*>(h + (long long)s3 * F1 + fl * 4);
        acc.x += w0 * v0.x; acc.y += w0 * v0.y; acc.z += w0 * v0.z; acc.w += w0 * v0.w;
        acc.x += w1 * v1.x; acc.y += w1 * v1.y; acc.z += w1 * v1.z; acc.w += w1 * v1.w;
        acc.x += w2 * v2.x; acc.y += w2 * v2.y; acc.z += w2 * v2.z; acc.w += w2 * v2.w;
        acc.x += w3 * v3.x; acc.y += w3 * v3.y; acc.z += w3 * v3.z; acc.w += w3 * v3.w;
    }
    for (; j < r1; j += 2) {
        int s = row[j];
        float w = g_dinv[s];
        float4 vv = *reinterpret_cast<const float4*>(h + (long long)s * F1 + fl * 4);
        acc.x += w * vv.x; acc.y += w * vv.y; acc.z += w * vv.z; acc.w += w * vv.w;
    }

    acc.x += __shfl_xor_sync(0xffffffffu, acc.x, 16);
    acc.y += __shfl_xor_sync(0xffffffffu, acc.y, 16);
    acc.z += __shfl_xor_sync(0xffffffffu, acc.z, 16);
    acc.w += __shfl_xor_sync(0xffffffffu, acc.w, 16);
    if (half == 0) {
        acc.x *= div; acc.y *= div; acc.z *= div; acc.w *= div;
        *reinterpret_cast<float4*>(g + (long long)v * F1 + fl * 4) = acc;
    }
}

__global__ void __launch_bounds__(256)
prop32_kernel(const float* __restrict__ h, float* __restrict__ g, int n)
{
    const int v = (blockIdx.x * blockDim.x + threadIdx.x) >> 5;
    if (v >= n) return;
    const int lane = threadIdx.x & 31;
    const int q  = lane >> 3;
    const int fl = lane & 7;
    const int r1 = min(g_cnt[v], PAD);
    const float div = g_dinv[v];
    const int* __restrict__ row = g_ell + (long long)v * PAD;

    float4 acc = make_float4(0.f, 0.f, 0.f, 0.f);
    if (q == 0) {
        acc = *reinterpret_cast<const float4*>(h + (long long)v * F2 + fl * 4);
        acc.x *= div; acc.y *= div; acc.z *= div; acc.w *= div;
    }

    int j = q;
    for (; j + 12 < r1; j += 16) {
        int s0 = row[j], s1 = row[j + 4], s2 = row[j + 8], s3 = row[j + 12];
        float w0 = g_dinv[s0], w1 = g_dinv[s1], w2 = g_dinv[s2], w3 = g_dinv[s3];
        float4 v0 = *reinterpret_cast<const float4*>(h + (long long)s0 * F2 + fl * 4);
        float4 v1 = *reinterpret_cast<const float4*>(h + (long long)s1 * F2 + fl * 4);
        float4 v2 = *reinterpret_cast<const float4*>(h + (long long)s2 * F2 + fl * 4);
        float4 v3 = *reinterpret_cast<const float4*>(h + (long long)s3 * F2 + fl * 4);
        acc.x += w0 * v0.x; acc.y += w0 * v0.y; acc.z += w0 * v0.z; acc.w += w0 * v0.w;
        acc.x += w1 * v1.x; acc.y += w1 * v1.y; acc.z += w1 * v1.z; acc.w += w1 * v1.w;
        acc.x += w2 * v2.x; acc.y += w2 * v2.y; acc.z += w2 * v2.z; acc.w += w2 * v2.w;
        acc.x += w3 * v3.x; acc.y += w3 * v3.y; acc.z += w3 * v3.z; acc.w += w3 * v3.w;
    }
    for (; j < r1; j += 4) {
        int s = row[j];
        float w = g_dinv[s];
        float4 vv = *reinterpret_cast<const float4*>(h + (long long)s * F2 + fl * 4);
        acc.x += w * vv.x; acc.y += w * vv.y; acc.z += w * vv.z; acc.w += w * vv.w;
    }

#pragma unroll
    for (int o = 8; o <= 16; o <<= 1) {
        acc.x += __shfl_xor_sync(0xffffffffu, acc.x, o);
        acc.y += __shfl_xor_sync(0xffffffffu, acc.y, o);
        acc.z += __shfl_xor_sync(0xffffffffu, acc.z, o);
        acc.w += __shfl_xor_sync(0xffffffffu, acc.w, o);
    }
    if (q == 0) {
        acc.x *= div; acc.y *= div; acc.z *= div; acc.w *= div;
        *reinterpret_cast<float4*>(g + (long long)v * F2 + fl * 4) = acc;
    }
}

// ---------------- launcher (forked-stream capture) ----------------
extern "C" void kernel_launch(void* const* d_in, const int* in_sizes, int n_in,
                              void* d_out, int out_size)
{
    const float* x  = (const float*)d_in[0];
    const int*   ei = (const int*)  d_in[1];
    const float* W1 = (const float*)d_in[2];
    const float* b1 = (const float*)d_in[3];
    const float* W2 = (const float*)d_in[4];
    const float* b2 = (const float*)d_in[5];
    const float* Wl = (const float*)d_in[6];
    const float* bl = (const float*)d_in[7];
    float* out = (float*)d_out;

    const int n = in_sizes[0] / DIN;
    const int E = in_sizes[1] / 2;

    void *ph1, *pa1, *ph2, *pa2;
    cudaGetSymbolAddress(&ph1, g_h1);
    cudaGetSymbolAddress(&pa1, g_a1);
    cudaGetSymbolAddress(&ph2, g_h2);
    cudaGetSymbolAddress(&pa2, g_a2);
    float* h1 = (float*)ph1; float* a1 = (float*)pa1;
    float* h2 = (float*)ph2; float* a2 = (float*)pa2;

    const int nblk = (n + 63) / 64;      // TM=64
    const int pblk = (n * 32 + 255) / 256;

    cudaStream_t s2;
    cudaStreamCreateWithFlags(&s2, cudaStreamNonBlocking);
    cudaEvent_t evFork, evJoin;
    cudaEventCreateWithFlags(&evFork, cudaEventDisableTiming);
    cudaEventCreateWithFlags(&evJoin, cudaEventDisableTiming);

    // fork: ELL build on s2, concurrent with gemm1 on the main stream
    cudaEventRecord(evFork, 0);
    cudaStreamWaitEvent(s2, evFork, 0);

    detect_kernel<<<1, 256, 0, s2>>>(ei, E);
    scatter_count_kernel<<<(E + 255) / 256, 256, 0, s2>>>(ei, E);
    dinv_kernel<<<(n + 255) / 256, 256, 0, s2>>>(n);
    cudaEventRecord(evJoin, s2);

    // main stream: layer-1 GEMM overlaps ELL build
    gemm_rt3<DIN, F1, 64, false, false, false>
        <<<dim3(nblk, 1), 128>>>(x, W1, nullptr, nullptr, h1, n);

    cudaStreamWaitEvent(0, evJoin, 0);

    prop64_kernel<<<pblk, 256>>>(h1, a1, n);
    gemm_rt3<F1, F2, 32, true, false, false>
        <<<dim3(nblk, 1), 64>>>(a1, W2, b1, nullptr, h2, n);
    prop32_kernel<<<pblk, 256>>>(h2, a2, n);
    // gemm3 also re-zeroes g_cnt for the next replay (ZCNT=true)
    gemm_rt3<F2, DOUT, 64, true, true, true>
        <<<dim3(nblk, 2), 128>>>(a2, Wl, b2, bl, out, n);

    cudaEventDestroy(evFork);
    cudaEventDestroy(evJoin);
    cudaStreamDestroy(s2);
}

// round 13
// speedup vs baseline: 1.0587x; 1.0587x over previous
#include <cuda_runtime.h>

// ---------------- problem-size constants ----------------
#define NMAX 50000
#define EMAX 800000
#define F1   64
#define F2   32
#define DIN  128
#define DOUT 128
#define PAD  128          // ELL row capacity (Poisson(16) max deg ~45; huge margin)

// ---------------- device scratch ----------------
__device__ int   g_cnt[NMAX];             // zero-init at load; re-zeroed by gemm3 tail
__device__ float g_dinv[NMAX];
__device__ int   g_ell[(long long)NMAX * PAD];
__device__ float g_h1[NMAX * F1];
__device__ float g_a1[NMAX * F1];
__device__ float g_h2[NMAX * F2];
__device__ float g_a2[NMAX * F2];
__device__ int   g_is64;

// ---------------- f32x2 helpers ----------------
__device__ __forceinline__ void fma2(unsigned long long& d,
                                     unsigned long long a,
                                     unsigned long long b) {
    asm("fma.rn.f32x2 %0, %1, %2, %0;" : "+l"(d) : "l"(a), "l"(b));
}
__device__ __forceinline__ unsigned long long dup2(float w) {
    unsigned long long r;
    asm("mov.b64 %0, {%1, %1};" : "=l"(r) : "f"(w));
    return r;
}
__device__ __forceinline__ float lo32(unsigned long long v) {
    return __uint_as_float((unsigned)(v & 0xffffffffull));
}
__device__ __forceinline__ float hi32(unsigned long long v) {
    return __uint_as_float((unsigned)(v >> 32));
}

// ---------------- edge-index dtype detection (1 block) ----------------
__global__ void detect_kernel(const int* __restrict__ w, int E) {
    __shared__ int any_nonzero;
    if (threadIdx.x == 0) any_nonzero = 0;
    __syncthreads();
    int stride = (2 * E) / 512;
    int idx = 2 * (threadIdx.x * stride) + 1;
    if (w[idx] != 0) atomicOr(&any_nonzero, 1);
    __syncthreads();
    if (threadIdx.x == 0) g_is64 = any_nonzero ? 0 : 1;
}

// ---------------- ELL build: count + scatter in ONE pass ----------------
__global__ void scatter_count_kernel(const int* __restrict__ w, int E) {
    int e = blockIdx.x * blockDim.x + threadIdx.x;
    if (e >= E) return;
    int s, d;
    if (g_is64) { s = w[2 * e]; d = w[2 * (E + e)]; }
    else        { s = w[e];     d = w[E + e];       }
    int p = atomicAdd(&g_cnt[d], 1);
    if (p < PAD) g_ell[(long long)d * PAD + p] = s;
}

__global__ void dinv_kernel(int n) {
    int i = blockIdx.x * blockDim.x + threadIdx.x;
    if (i < n) g_dinv[i] = rsqrtf((float)(g_cnt[i] + 1));   // +1 self loop
}

// ---------------- f32x2 GEMM: 8 nodes x 8 cols per thread (round-11) --------
// cnt: if non-null, blocks with blockIdx.y==0 zero cnt[nb..nb+TM) at entry.
template<int KIN, int KOUT, int TN, bool INACT, bool OBIAS>
__global__ void __launch_bounds__((TN / 8) * 16)
gemm_rt2(const float* __restrict__ A, const float* __restrict__ W,
         const float* __restrict__ ib, const float* __restrict__ ob,
         float* __restrict__ H, int n, int* cnt)
{
    constexpr int TM = 128;
    constexpr int TK = (KIN < 32) ? KIN : 32;
    constexpr int NTX = TN / 8;
    constexpr int NTY = TM / 8;
    constexpr int NTH = NTX * NTY;
    constexpr int XPITCH = TM + 4;

    __shared__ float Xs[TK * XPITCH];
    __shared__ float Ws[TK * TN];

    const int tid = threadIdx.x;
    const int tx = tid % NTX;
    const int ty = tid / NTX;
    const int nb = blockIdx.x * TM;
    const int jn = blockIdx.y * TN;
    const int valid = min(TM, n - nb);

    if (cnt != nullptr && blockIdx.y == 0 && tid < TM) {
        int idx = nb + tid;
        if (idx < n) cnt[idx] = 0;
    }

    unsigned long long acc[4][8];
#pragma unroll
    for (int i = 0; i < 4; i++)
#pragma unroll
        for (int j = 0; j < 8; j++) acc[i][j] = 0ull;

    for (int kt = 0; kt < KIN; kt += TK) {
#pragma unroll
        for (int idx = tid; idx < TM * TK / 4; idx += NTH) {
            int r  = idx / (TK / 4);
            int kq = idx % (TK / 4);
            float4 v = make_float4(0.f, 0.f, 0.f, 0.f);
            if (r < valid)
                v = *reinterpret_cast<const float4*>(
                        A + (long long)(nb + r) * KIN + kt + kq * 4);
            if (INACT) {
                const float4 bb = *reinterpret_cast<const float4*>(ib + kt + kq * 4);
                v.x = fmaxf(v.x + bb.x, 0.f);
                v.y = fmaxf(v.y + bb.y, 0.f);
                v.z = fmaxf(v.z + bb.z, 0.f);
                v.w = fmaxf(v.w + bb.w, 0.f);
            }
            Xs[(kq * 4 + 0) * XPITCH + r] = v.x;
            Xs[(kq * 4 + 1) * XPITCH + r] = v.y;
            Xs[(kq * 4 + 2) * XPITCH + r] = v.z;
            Xs[(kq * 4 + 3) * XPITCH + r] = v.w;
        }
#pragma unroll
        for (int idx = tid; idx < TK * TN / 4; idx += NTH) {
            int kk = idx / (TN / 4);
            int jq = idx % (TN / 4);
            *reinterpret_cast<float4*>(Ws + kk * TN + jq * 4) =
                *reinterpret_cast<const float4*>(
                    W + (long long)(kt + kk) * KOUT + jn + jq * 4);
        }
        __syncthreads();

#pragma unroll
        for (int kk = 0; kk < TK; kk++) {
            const ulonglong2 pa01 = *reinterpret_cast<const ulonglong2*>(
                Xs + kk * XPITCH + ty * 8);
            const ulonglong2 pa23 = *reinterpret_cast<const ulonglong2*>(
                Xs + kk * XPITCH + ty * 8 + 4);
            const float4 b0 = *reinterpret_cast<const float4*>(Ws + kk * TN + tx * 8);
            const float4 b1 = *reinterpret_cast<const float4*>(Ws + kk * TN + tx * 8 + 4);
            unsigned long long pb[8];
            pb[0] = dup2(b0.x); pb[1] = dup2(b0.y); pb[2] = dup2(b0.z); pb[3] = dup2(b0.w);
            pb[4] = dup2(b1.x); pb[5] = dup2(b1.y); pb[6] = dup2(b1.z); pb[7] = dup2(b1.w);

            unsigned long long pa[4] = { pa01.x, pa01.y, pa23.x, pa23.y };
#pragma unroll
            for (int p = 0; p < 4; p++)
#pragma unroll
                for (int j = 0; j < 8; j++)
                    fma2(acc[p][j], pa[p], pb[j]);
        }
        __syncthreads();
    }

    float4 bo0 = make_float4(0.f, 0.f, 0.f, 0.f);
    float4 bo1 = make_float4(0.f, 0.f, 0.f, 0.f);
    if (OBIAS) {
        bo0 = *reinterpret_cast<const float4*>(ob + jn + tx * 8);
        bo1 = *reinterpret_cast<const float4*>(ob + jn + tx * 8 + 4);
    }
#pragma unroll
    for (int p = 0; p < 4; p++) {
#pragma unroll
        for (int half = 0; half < 2; half++) {
            int node = nb + ty * 8 + p * 2 + half;
            if (node < n) {
                float4 v0, v1;
                if (half == 0) {
                    v0 = make_float4(lo32(acc[p][0]), lo32(acc[p][1]),
                                     lo32(acc[p][2]), lo32(acc[p][3]));
                    v1 = make_float4(lo32(acc[p][4]), lo32(acc[p][5]),
                                     lo32(acc[p][6]), lo32(acc[p][7]));
                } else {
                    v0 = make_float4(hi32(acc[p][0]), hi32(acc[p][1]),
                                     hi32(acc[p][2]), hi32(acc[p][3]));
                    v1 = make_float4(hi32(acc[p][4]), hi32(acc[p][5]),
                                     hi32(acc[p][6]), hi32(acc[p][7]));
                }
                v0.x += bo0.x; v0.y += bo0.y; v0.z += bo0.z; v0.w += bo0.w;
                v1.x += bo1.x; v1.y += bo1.y; v1.z += bo1.z; v1.w += bo1.w;
                float* dst = H + (long long)node * KOUT + jn + tx * 8;
                *reinterpret_cast<float4*>(dst)     = v0;
                *reinterpret_cast<float4*>(dst + 4) = v1;
            }
        }
    }
}

// ---------------- ELL gather propagation: multi-stream warps ----------------
// node range [v0, vend)
__global__ void __launch_bounds__(256)
prop64_kernel(const float* __restrict__ h, float* __restrict__ g, int v0, int vend)
{
    const int v = v0 + ((blockIdx.x * blockDim.x + threadIdx.x) >> 5);
    if (v >= vend) return;
    const int lane = threadIdx.x & 31;
    const int half = lane >> 4;
    const int fl   = lane & 15;
    const int r1 = min(g_cnt[v], PAD);
    const float div = g_dinv[v];
    const int* __restrict__ row = g_ell + (long long)v * PAD;

    float4 acc = make_float4(0.f, 0.f, 0.f, 0.f);
    if (half == 0) {
        acc = *reinterpret_cast<const float4*>(h + (long long)v * F1 + fl * 4);
        acc.x *= div; acc.y *= div; acc.z *= div; acc.w *= div;
    }

    int j = half;
    for (; j + 6 < r1; j += 8) {
        int s0 = row[j], s1 = row[j + 2], s2 = row[j + 4], s3 = row[j + 6];
        float w0 = g_dinv[s0], w1 = g_dinv[s1], w2 = g_dinv[s2], w3 = g_dinv[s3];
        float4 v0_ = *reinterpret_cast<const float4*>(h + (long long)s0 * F1 + fl * 4);
        float4 v1_ = *reinterpret_cast<const float4*>(h + (long long)s1 * F1 + fl * 4);
        float4 v2_ = *reinterpret_cast<const float4*>(h + (long long)s2 * F1 + fl * 4);
        float4 v3_ = *reinterpret_cast<const float4*>(h + (long long)s3 * F1 + fl * 4);
        acc.x += w0 * v0_.x; acc.y += w0 * v0_.y; acc.z += w0 * v0_.z; acc.w += w0 * v0_.w;
        acc.x += w1 * v1_.x; acc.y += w1 * v1_.y; acc.z += w1 * v1_.z; acc.w += w1 * v1_.w;
        acc.x += w2 * v2_.x; acc.y += w2 * v2_.y; acc.z += w2 * v2_.z; acc.w += w2 * v2_.w;
        acc.x += w3 * v3_.x; acc.y += w3 * v3_.y; acc.z += w3 * v3_.z; acc.w += w3 * v3_.w;
    }
    for (; j < r1; j += 2) {
        int s = row[j];
        float w = g_dinv[s];
        float4 vv = *reinterpret_cast<const float4*>(h + (long long)s * F1 + fl * 4);
        acc.x += w * vv.x; acc.y += w * vv.y; acc.z += w * vv.z; acc.w += w * vv.w;
    }

    acc.x += __shfl_xor_sync(0xffffffffu, acc.x, 16);
    acc.y += __shfl_xor_sync(0xffffffffu, acc.y, 16);
    acc.z += __shfl_xor_sync(0xffffffffu, acc.z, 16);
    acc.w += __shfl_xor_sync(0xffffffffu, acc.w, 16);
    if (half == 0) {
        acc.x *= div; acc.y *= div; acc.z *= div; acc.w *= div;
        *reinterpret_cast<float4*>(g + (long long)v * F1 + fl * 4) = acc;
    }
}

__global__ void __launch_bounds__(256)
prop32_kernel(const float* __restrict__ h, float* __restrict__ g, int v0, int vend)
{
    const int v = v0 + ((blockIdx.x * blockDim.x + threadIdx.x) >> 5);
    if (v >= vend) return;
    const int lane = threadIdx.x & 31;
    const int q  = lane >> 3;
    const int fl = lane & 7;
    const int r1 = min(g_cnt[v], PAD);
    const float div = g_dinv[v];
    const int* __restrict__ row = g_ell + (long long)v * PAD;

    float4 acc = make_float4(0.f, 0.f, 0.f, 0.f);
    if (q == 0) {
        acc = *reinterpret_cast<const float4*>(h + (long long)v * F2 + fl * 4);
        acc.x *= div; acc.y *= div; acc.z *= div; acc.w *= div;
    }

    int j = q;
    for (; j + 12 < r1; j += 16) {
        int s0 = row[j], s1 = row[j + 4], s2 = row[j + 8], s3 = row[j + 12];
        float w0 = g_dinv[s0], w1 = g_dinv[s1], w2 = g_dinv[s2], w3 = g_dinv[s3];
        float4 v0_ = *reinterpret_cast<const float4*>(h + (long long)s0 * F2 + fl * 4);
        float4 v1_ = *reinterpret_cast<const float4*>(h + (long long)s1 * F2 + fl * 4);
        float4 v2_ = *reinterpret_cast<const float4*>(h + (long long)s2 * F2 + fl * 4);
        float4 v3_ = *reinterpret_cast<const float4*>(h + (long long)s3 * F2 + fl * 4);
        acc.x += w0 * v0_.x; acc.y += w0 * v0_.y; acc.z += w0 * v0_.z; acc.w += w0 * v0_.w;
        acc.x += w1 * v1_.x; acc.y += w1 * v1_.y; acc.z += w1 * v1_.z; acc.w += w1 * v1_.w;
        acc.x += w2 * v2_.x; acc.y += w2 * v2_.y; acc.z += w2 * v2_.z; acc.w += w2 * v2_.w;
        acc.x += w3 * v3_.x; acc.y += w3 * v3_.y; acc.z += w3 * v3_.z; acc.w += w3 * v3_.w;
    }
    for (; j < r1; j += 4) {
        int s = row[j];
        float w = g_dinv[s];
        float4 vv = *reinterpret_cast<const float4*>(h + (long long)s * F2 + fl * 4);
        acc.x += w * vv.x; acc.y += w * vv.y; acc.z += w * vv.z; acc.w += w * vv.w;
    }

#pragma unroll
    for (int o = 8; o <= 16; o <<= 1) {
        acc.x += __shfl_xor_sync(0xffffffffu, acc.x, o);
        acc.y += __shfl_xor_sync(0xffffffffu, acc.y, o);
        acc.z += __shfl_xor_sync(0xffffffffu, acc.z, o);
        acc.w += __shfl_xor_sync(0xffffffffu, acc.w, o);
    }
    if (q == 0) {
        acc.x *= div; acc.y *= div; acc.z *= div; acc.w *= div;
        *reinterpret_cast<float4*>(g + (long long)v * F2 + fl * 4) = acc;
    }
}

// ---------------- launcher (forked-stream, half-pipelined) ----------------
extern "C" void kernel_launch(void* const* d_in, const int* in_sizes, int n_in,
                              void* d_out, int out_size)
{
    const float* x  = (const float*)d_in[0];
    const int*   ei = (const int*)  d_in[1];
    const float* W1 = (const float*)d_in[2];
    const float* b1 = (const float*)d_in[3];
    const float* W2 = (const float*)d_in[4];
    const float* b2 = (const float*)d_in[5];
    const float* Wl = (const float*)d_in[6];
    const float* bl = (const float*)d_in[7];
    float* out = (float*)d_out;

    const int n = in_sizes[0] / DIN;
    const int E = in_sizes[1] / 2;

    void *ph1, *pa1, *ph2, *pa2, *pcnt;
    cudaGetSymbolAddress(&ph1, g_h1);
    cudaGetSymbolAddress(&pa1, g_a1);
    cudaGetSymbolAddress(&ph2, g_h2);
    cudaGetSymbolAddress(&pa2, g_a2);
    cudaGetSymbolAddress(&pcnt, g_cnt);
    float* h1 = (float*)ph1; float* a1 = (float*)pa1;
    float* h2 = (float*)ph2; float* a2 = (float*)pa2;
    int* cnt = (int*)pcnt;

    // split nodes into half A (multiple of 128) and half B
    const int nA = ((n / 2 + 127) / 128) * 128;
    const int nB = n - nA;
    const int blkA = nA / 128;
    const int blkB = (nB + 127) / 128;
    const int nblk = (n + 127) / 128;
    const int pA = (nA * 32 + 255) / 256;
    const int pB = (nB * 32 + 255) / 256;

    cudaStream_t s2;
    cudaStreamCreateWithFlags(&s2, cudaStreamNonBlocking);
    cudaEvent_t evFork, evJoin, evPA, evG2A, evP3A, evG3A;
    cudaEventCreateWithFlags(&evFork, cudaEventDisableTiming);
    cudaEventCreateWithFlags(&evJoin, cudaEventDisableTiming);
    cudaEventCreateWithFlags(&evPA,   cudaEventDisableTiming);
    cudaEventCreateWithFlags(&evG2A,  cudaEventDisableTiming);
    cudaEventCreateWithFlags(&evP3A,  cudaEventDisableTiming);
    cudaEventCreateWithFlags(&evG3A,  cudaEventDisableTiming);

    // fork: ELL build on s2, concurrent with gemm1 on main
    cudaEventRecord(evFork, 0);
    cudaStreamWaitEvent(s2, evFork, 0);

    detect_kernel<<<1, 256, 0, s2>>>(ei, E);
    scatter_count_kernel<<<(E + 255) / 256, 256, 0, s2>>>(ei, E);
    dinv_kernel<<<(n + 255) / 256, 256, 0, s2>>>(n);
    cudaEventRecord(evJoin, s2);

    // main: gemm1 overlaps ELL build
    gemm_rt2<DIN, F1, 64, false, false>
        <<<dim3(nblk, 1), 128>>>(x, W1, nullptr, nullptr, h1, n, nullptr);

    cudaStreamWaitEvent(0, evJoin, 0);

    // prop64-A, then {gemm2-A on s2 || prop64-B on main}
    prop64_kernel<<<pA, 256>>>(h1, a1, 0, nA);
    cudaEventRecord(evPA, 0);
    cudaStreamWaitEvent(s2, evPA, 0);
    gemm_rt2<F1, F2, 32, true, false>
        <<<dim3(blkA, 1), 64, 0, s2>>>(a1, W2, b1, nullptr, h2, nA, nullptr);
    cudaEventRecord(evG2A, s2);

    prop64_kernel<<<pB, 256>>>(h1, a1, nA, n);
    gemm_rt2<F1, F2, 32, true, false>
        <<<dim3(blkB, 1), 64>>>(a1 + (long long)nA * F1, W2, b1, nullptr,
                                h2 + (long long)nA * F2, nB, nullptr);
    cudaStreamWaitEvent(0, evG2A, 0);

    // prop32-A, then {gemm3-A on s2 || prop32-B on main}
    prop32_kernel<<<pA, 256>>>(h2, a2, 0, nA);
    cudaEventRecord(evP3A, 0);
    cudaStreamWaitEvent(s2, evP3A, 0);
    gemm_rt2<F2, DOUT, 64, true, true>
        <<<dim3(blkA, 2), 128, 0, s2>>>(a2, Wl, b2, bl, out, nA, cnt);
    cudaEventRecord(evG3A, s2);

    prop32_kernel<<<pB, 256>>>(h2, a2, nA, n);
    gemm_rt2<F2, DOUT, 64, true, true>
        <<<dim3(blkB, 2), 128>>>(a2 + (long long)nA * F2, Wl, b2, bl,
                                 out + (long long)nA * DOUT, nB, cnt + nA);
    cudaStreamWaitEvent(0, evG3A, 0);

    cudaEventDestroy(evFork);
    cudaEventDestroy(evJoin);
    cudaEventDestroy(evPA);
    cudaEventDestroy(evG2A);
    cudaEventDestroy(evP3A);
    cudaEventDestroy(evG3A);
    cudaStreamDestroy(s2);
}